// round 1
// baseline (speedup 1.0000x reference)
#include <cuda_runtime.h>
#include <math.h>

#define BATCH 16
#define NQ    64
#define NSEQ  4096
#define DH    128
#define SCALE 0.08838834764831845f   // 1/sqrt(128)

// Scratch: attention weights a[b,q,n] (scores in-place -> softmax in-place). 16.7 MB.
__device__ float g_attn[(size_t)BATCH * NQ * NSEQ];

// ---------------------------------------------------------------------------
// Kernel 1: scores S[b,q,n] = (Q[b,q,:] . K[b,n,:]) * SCALE
// grid (32 n-tiles of 128, 16 batches), 256 threads.
// Thread (ty=tid/32, tx=tid%32) computes 8 q-rows x 4 n-cols.
// ---------------------------------------------------------------------------
__global__ void scores_kernel(const float* __restrict__ Q,
                              const float* __restrict__ K) {
    __shared__ float Qs[64][33];
    __shared__ float Kt[128][33];

    const int b   = blockIdx.y;
    const int nt  = blockIdx.x;
    const int tid = threadIdx.x;
    const int ty  = tid >> 5;   // 0..7  -> q rows ty*8..ty*8+7
    const int tx  = tid & 31;   // 0..31 -> n cols tx*4..tx*4+3

    const float* Qb = Q + (size_t)b * NQ * DH;
    const float* Kb = K + ((size_t)b * NSEQ + (size_t)nt * 128) * DH;

    float acc[8][4];
    #pragma unroll
    for (int i = 0; i < 8; i++)
        #pragma unroll
        for (int j = 0; j < 4; j++) acc[i][j] = 0.f;

    for (int d0 = 0; d0 < DH; d0 += 32) {
        for (int i = tid; i < 64 * 32; i += 256) {
            int r = i >> 5, c = i & 31;
            Qs[r][c] = Qb[r * DH + d0 + c];
        }
        for (int i = tid; i < 128 * 32; i += 256) {
            int r = i >> 5, c = i & 31;
            Kt[r][c] = Kb[r * DH + d0 + c];
        }
        __syncthreads();

        #pragma unroll 8
        for (int dd = 0; dd < 32; dd++) {
            float qf[8], kf[4];
            #pragma unroll
            for (int i = 0; i < 8; i++) qf[i] = Qs[ty * 8 + i][dd];
            #pragma unroll
            for (int j = 0; j < 4; j++) kf[j] = Kt[tx * 4 + j][dd];
            #pragma unroll
            for (int i = 0; i < 8; i++)
                #pragma unroll
                for (int j = 0; j < 4; j++)
                    acc[i][j] += qf[i] * kf[j];
        }
        __syncthreads();
    }

    float* S = g_attn + ((size_t)b * NQ) * NSEQ + (size_t)nt * 128;
    #pragma unroll
    for (int i = 0; i < 8; i++)
        #pragma unroll
        for (int j = 0; j < 4; j++)
            S[(size_t)(ty * 8 + i) * NSEQ + tx * 4 + j] = acc[i][j] * SCALE;
}

// ---------------------------------------------------------------------------
// Kernel 2: in-place softmax over n (4096) per (b,q) row. grid 1024, 256 thr.
// ---------------------------------------------------------------------------
__global__ void softmax_kernel() {
    const int row = blockIdx.x;
    float* p = g_attn + (size_t)row * NSEQ;
    const int tid = threadIdx.x;

    float v[16];
    float m = -1e30f;
    #pragma unroll
    for (int i = 0; i < 16; i++) {
        v[i] = p[tid + i * 256];
        m = fmaxf(m, v[i]);
    }

    __shared__ float red[256];
    red[tid] = m;
    __syncthreads();
    #pragma unroll
    for (int s = 128; s > 0; s >>= 1) {
        if (tid < s) red[tid] = fmaxf(red[tid], red[tid + s]);
        __syncthreads();
    }
    m = red[0];
    __syncthreads();

    float sum = 0.f;
    #pragma unroll
    for (int i = 0; i < 16; i++) {
        v[i] = __expf(v[i] - m);
        sum += v[i];
    }
    red[tid] = sum;
    __syncthreads();
    #pragma unroll
    for (int s = 128; s > 0; s >>= 1) {
        if (tid < s) red[tid] += red[tid + s];
        __syncthreads();
    }
    const float inv = 1.0f / red[0];
    #pragma unroll
    for (int i = 0; i < 16; i++) p[tid + i * 256] = v[i] * inv;
}

// ---------------------------------------------------------------------------
// Kernel 3: per (b,q) CTA:
//   C[v,k]   = sum_n a_n V[n,v] K[n,k]       (128x128x4096 outer-product GEMM)
//   vout[v]  = sum_n a_n V[n,v]
//   wk[k]    = sum_n a_n K[n,k]
//   J[v,k]   = SCALE * (C - vout*wk)
// 256 threads = 16x16 grid, 8x8 micro-tile per thread. vout/wk accumulated
// redundantly per-thread (each thread covers all n), so epilogue needs no
// cross-thread reduction.
// ---------------------------------------------------------------------------
__global__ __launch_bounds__(256, 2) void jac_kernel(const float* __restrict__ K,
                                                     const float* __restrict__ V,
                                                     float* __restrict__ out) {
    __shared__ float Ks[32 * 128];
    __shared__ float Vs[32 * 128];
    __shared__ float as[32];

    const int bq = blockIdx.x;
    const int b  = bq >> 6;
    const float* a  = g_attn + (size_t)bq * NSEQ;
    const float* Kb = K + (size_t)b * NSEQ * DH;
    const float* Vb = V + (size_t)b * NSEQ * DH;

    const int tid = threadIdx.x;
    const int ty  = tid >> 4;   // 0..15 -> v rows ty*8..+7
    const int tx  = tid & 15;   // 0..15 -> k cols tx*8..+7

    float C[8][8];
    float vout[8], wk[8];
    #pragma unroll
    for (int i = 0; i < 8; i++) {
        vout[i] = 0.f;
        wk[i] = 0.f;
        #pragma unroll
        for (int j = 0; j < 8; j++) C[i][j] = 0.f;
    }

    for (int n0 = 0; n0 < NSEQ; n0 += 32) {
        const float4* Kg = (const float4*)(Kb + (size_t)n0 * DH);
        const float4* Vg = (const float4*)(Vb + (size_t)n0 * DH);
        float4* Ks4 = (float4*)Ks;
        float4* Vs4 = (float4*)Vs;
        #pragma unroll
        for (int i = 0; i < 4; i++) {
            Ks4[tid + i * 256] = Kg[tid + i * 256];
            Vs4[tid + i * 256] = Vg[tid + i * 256];
        }
        if (tid < 32) as[tid] = a[n0 + tid];
        __syncthreads();

        #pragma unroll 2
        for (int n = 0; n < 32; n++) {
            const float la = as[n];
            const float4 v0 = *(const float4*)&Vs[n * 128 + ty * 8];
            const float4 v1 = *(const float4*)&Vs[n * 128 + ty * 8 + 4];
            const float4 k0 = *(const float4*)&Ks[n * 128 + tx * 8];
            const float4 k1 = *(const float4*)&Ks[n * 128 + tx * 8 + 4];
            const float vf[8] = {v0.x, v0.y, v0.z, v0.w, v1.x, v1.y, v1.z, v1.w};
            const float kf[8] = {k0.x, k0.y, k0.z, k0.w, k1.x, k1.y, k1.z, k1.w};
            float av[8];
            #pragma unroll
            for (int i = 0; i < 8; i++) {
                av[i] = la * vf[i];
                vout[i] += av[i];
            }
            #pragma unroll
            for (int j = 0; j < 8; j++) wk[j] += la * kf[j];
            #pragma unroll
            for (int i = 0; i < 8; i++)
                #pragma unroll
                for (int j = 0; j < 8; j++)
                    C[i][j] += av[i] * kf[j];
        }
        __syncthreads();
    }

    float* o = out + (size_t)bq * DH * DH;
    #pragma unroll
    for (int i = 0; i < 8; i++) {
        #pragma unroll
        for (int j = 0; j < 8; j++) {
            o[(size_t)(ty * 8 + i) * DH + tx * 8 + j] =
                SCALE * (C[i][j] - vout[i] * wk[j]);
        }
    }
}

// ---------------------------------------------------------------------------
// Launch: inputs per metadata order: query (16,64,128), keys (16,4096,128),
// values (16,4096,128). Output: (16,64,128,128) fp32.
// ---------------------------------------------------------------------------
extern "C" void kernel_launch(void* const* d_in, const int* in_sizes, int n_in,
                              void* d_out, int out_size) {
    const float* Q = (const float*)d_in[0];
    const float* K = (const float*)d_in[1];
    const float* V = (const float*)d_in[2];
    float* out = (float*)d_out;

    scores_kernel<<<dim3(32, BATCH), 256>>>(Q, K);
    softmax_kernel<<<BATCH * NQ, 256>>>();
    jac_kernel<<<BATCH * NQ, 256>>>(K, V, out);
}

// round 2
// speedup vs baseline: 3.5115x; 3.5115x over previous
#include <cuda_runtime.h>
#include <math.h>
#include <stdint.h>

#define BATCH 16
#define NQ    64
#define NSEQ  4096
#define DH    128
#define SCALE 0.08838834764831845f   // 1/sqrt(128)

// Scratch: attention weights a[b,q,n]. 16.7 MB.
__device__ float g_attn[(size_t)BATCH * NQ * NSEQ];

__device__ __forceinline__ uint32_t f2tf32(float f) {
    uint32_t r;
    asm("cvt.rna.tf32.f32 %0, %1;" : "=r"(r) : "f"(f));
    return r;
}

__device__ __forceinline__ void mma_tf32(float c[4], uint32_t a0, uint32_t a1,
                                         uint32_t a2, uint32_t a3,
                                         uint32_t b0, uint32_t b1) {
    asm volatile(
        "mma.sync.aligned.m16n8k8.row.col.f32.tf32.tf32.f32 "
        "{%0,%1,%2,%3}, {%4,%5,%6,%7}, {%8,%9}, {%0,%1,%2,%3};"
        : "+f"(c[0]), "+f"(c[1]), "+f"(c[2]), "+f"(c[3])
        : "r"(a0), "r"(a1), "r"(a2), "r"(a3), "r"(b0), "r"(b1));
}

// ---------------------------------------------------------------------------
// Kernel 1: scores S[b,q,n] = (Q[b,q,:] . K[b,n,:]) * SCALE   (unchanged)
// ---------------------------------------------------------------------------
__global__ void scores_kernel(const float* __restrict__ Q,
                              const float* __restrict__ K) {
    __shared__ float Qs[64][33];
    __shared__ float Kt[128][33];

    const int b   = blockIdx.y;
    const int nt  = blockIdx.x;
    const int tid = threadIdx.x;
    const int ty  = tid >> 5;
    const int tx  = tid & 31;

    const float* Qb = Q + (size_t)b * NQ * DH;
    const float* Kb = K + ((size_t)b * NSEQ + (size_t)nt * 128) * DH;

    float acc[8][4];
    #pragma unroll
    for (int i = 0; i < 8; i++)
        #pragma unroll
        for (int j = 0; j < 4; j++) acc[i][j] = 0.f;

    for (int d0 = 0; d0 < DH; d0 += 32) {
        for (int i = tid; i < 64 * 32; i += 256) {
            int r = i >> 5, c = i & 31;
            Qs[r][c] = Qb[r * DH + d0 + c];
        }
        for (int i = tid; i < 128 * 32; i += 256) {
            int r = i >> 5, c = i & 31;
            Kt[r][c] = Kb[r * DH + d0 + c];
        }
        __syncthreads();

        #pragma unroll 8
        for (int dd = 0; dd < 32; dd++) {
            float qf[8], kf[4];
            #pragma unroll
            for (int i = 0; i < 8; i++) qf[i] = Qs[ty * 8 + i][dd];
            #pragma unroll
            for (int j = 0; j < 4; j++) kf[j] = Kt[tx * 4 + j][dd];
            #pragma unroll
            for (int i = 0; i < 8; i++)
                #pragma unroll
                for (int j = 0; j < 4; j++)
                    acc[i][j] += qf[i] * kf[j];
        }
        __syncthreads();
    }

    float* S = g_attn + ((size_t)b * NQ) * NSEQ + (size_t)nt * 128;
    #pragma unroll
    for (int i = 0; i < 8; i++)
        #pragma unroll
        for (int j = 0; j < 4; j++)
            S[(size_t)(ty * 8 + i) * NSEQ + tx * 4 + j] = acc[i][j] * SCALE;
}

// ---------------------------------------------------------------------------
// Kernel 2: in-place softmax over n per (b,q) row.   (unchanged)
// ---------------------------------------------------------------------------
__global__ void softmax_kernel() {
    const int row = blockIdx.x;
    float* p = g_attn + (size_t)row * NSEQ;
    const int tid = threadIdx.x;

    float v[16];
    float m = -1e30f;
    #pragma unroll
    for (int i = 0; i < 16; i++) {
        v[i] = p[tid + i * 256];
        m = fmaxf(m, v[i]);
    }

    __shared__ float red[256];
    red[tid] = m;
    __syncthreads();
    #pragma unroll
    for (int s = 128; s > 0; s >>= 1) {
        if (tid < s) red[tid] = fmaxf(red[tid], red[tid + s]);
        __syncthreads();
    }
    m = red[0];
    __syncthreads();

    float sum = 0.f;
    #pragma unroll
    for (int i = 0; i < 16; i++) {
        v[i] = __expf(v[i] - m);
        sum += v[i];
    }
    red[tid] = sum;
    __syncthreads();
    #pragma unroll
    for (int s = 128; s > 0; s >>= 1) {
        if (tid < s) red[tid] += red[tid + s];
        __syncthreads();
    }
    const float inv = 1.0f / red[0];
    #pragma unroll
    for (int i = 0; i < 16; i++) p[tid + i * 256] = v[i] * inv;
}

// ---------------------------------------------------------------------------
// Kernel 3 (tensor cores): per (b,q) CTA of 128 threads (4 warps, 2x2 tiling):
//   C[v,k]  = sum_n (a_n V[n,v]) K[n,k]   via mma.sync m16n8k8 tf32
//   vout[v] = sum_n a_n V[n,v]  , wk[k] = sum_n a_n K[n,k]   (fp32, in load phase)
//   J       = SCALE * (C - vout (x) wk)
// smem tiles [32][136] (stride 136 -> conflict-free fragment gathers).
// ---------------------------------------------------------------------------
#define KC     32
#define LDS_S  136

__global__ __launch_bounds__(128) void jac_kernel(const float* __restrict__ K,
                                                  const float* __restrict__ V,
                                                  float* __restrict__ out) {
    __shared__ float avs[KC * LDS_S];   // tf32 bits of a_n*V[n][v]
    __shared__ float kss[KC * LDS_S];   // tf32 bits of K[n][k]
    __shared__ float vred[4][128];
    __shared__ float kred[4][128];
    __shared__ float vout_s[128];
    __shared__ float wk_s[128];

    const int bq = blockIdx.x;
    const int b  = bq >> 6;
    const float* a  = g_attn + (size_t)bq * NSEQ;
    const float* Kb = K + (size_t)b * NSEQ * DH;
    const float* Vb = V + (size_t)b * NSEQ * DH;

    const int tid  = threadIdx.x;
    const int warp = tid >> 5;
    const int lane = tid & 31;
    const int g    = lane >> 2;      // groupID
    const int t    = lane & 3;       // threadID_in_group
    const int wm   = warp >> 1;      // 0..1  (64 v-rows)
    const int wn   = warp & 1;       // 0..1  (64 k-cols)

    const uint32_t* avs_u = (const uint32_t*)avs;
    const uint32_t* kss_u = (const uint32_t*)kss;

    float C[4][8][4];
    #pragma unroll
    for (int mt = 0; mt < 4; mt++)
        #pragma unroll
        for (int nt = 0; nt < 8; nt++)
            #pragma unroll
            for (int r = 0; r < 4; r++) C[mt][nt][r] = 0.f;

    float vout4[4] = {0.f, 0.f, 0.f, 0.f};
    float wk4[4]   = {0.f, 0.f, 0.f, 0.f};

    for (int n0 = 0; n0 < NSEQ; n0 += KC) {
        // ---- load + scale-by-a + tf32-convert into smem; accumulate vout/wk
        const float4* Vg = (const float4*)(Vb + (size_t)n0 * DH);
        const float4* Kg = (const float4*)(Kb + (size_t)n0 * DH);
        #pragma unroll
        for (int i = 0; i < 8; i++) {
            const int row = warp + 4 * i;           // 0..31
            const float av = __ldg(a + n0 + row);   // broadcast per warp
            float4 v4 = Vg[row * 32 + lane];
            float4 k4 = Kg[row * 32 + lane];
            float avx = av * v4.x, avy = av * v4.y, avz = av * v4.z, avw = av * v4.w;
            vout4[0] += avx; vout4[1] += avy; vout4[2] += avz; vout4[3] += avw;
            wk4[0] += av * k4.x; wk4[1] += av * k4.y;
            wk4[2] += av * k4.z; wk4[3] += av * k4.w;
            uint32_t* ap = (uint32_t*)&avs[row * LDS_S + lane * 4];
            uint32_t* kp = (uint32_t*)&kss[row * LDS_S + lane * 4];
            ap[0] = f2tf32(avx); ap[1] = f2tf32(avy);
            ap[2] = f2tf32(avz); ap[3] = f2tf32(avw);
            kp[0] = f2tf32(k4.x); kp[1] = f2tf32(k4.y);
            kp[2] = f2tf32(k4.z); kp[3] = f2tf32(k4.w);
        }
        __syncthreads();

        // ---- 4 k-steps of 8 over this chunk
        #pragma unroll
        for (int ks = 0; ks < 4; ks++) {
            const int r0 = (ks * 8 + t) * LDS_S;
            const int r1 = (ks * 8 + t + 4) * LDS_S;
            uint32_t bf[8][2];
            #pragma unroll
            for (int nt = 0; nt < 8; nt++) {
                const int col = wn * 64 + nt * 8 + g;
                bf[nt][0] = kss_u[r0 + col];
                bf[nt][1] = kss_u[r1 + col];
            }
            #pragma unroll
            for (int mt = 0; mt < 4; mt++) {
                const int m0 = wm * 64 + mt * 16 + g;
                uint32_t a0 = avs_u[r0 + m0];
                uint32_t a1 = avs_u[r0 + m0 + 8];
                uint32_t a2 = avs_u[r1 + m0];
                uint32_t a3 = avs_u[r1 + m0 + 8];
                #pragma unroll
                for (int nt = 0; nt < 8; nt++)
                    mma_tf32(C[mt][nt], a0, a1, a2, a3, bf[nt][0], bf[nt][1]);
            }
        }
        __syncthreads();
    }

    // ---- reduce vout/wk partials (4 warps each cover n = warp (mod 4))
    #pragma unroll
    for (int j = 0; j < 4; j++) {
        vred[warp][lane * 4 + j] = vout4[j];
        kred[warp][lane * 4 + j] = wk4[j];
    }
    __syncthreads();
    {
        vout_s[tid] = vred[0][tid] + vred[1][tid] + vred[2][tid] + vred[3][tid];
        wk_s[tid]   = kred[0][tid] + kred[1][tid] + kred[2][tid] + kred[3][tid];
    }
    __syncthreads();

    // ---- epilogue: J = SCALE * (C - vout (x) wk)
    float* o = out + (size_t)bq * DH * DH;
    #pragma unroll
    for (int mt = 0; mt < 4; mt++) {
        const int rbase = wm * 64 + mt * 16 + g;
        const float vo0 = vout_s[rbase];
        const float vo1 = vout_s[rbase + 8];
        #pragma unroll
        for (int nt = 0; nt < 8; nt++) {
            const int cbase = wn * 64 + nt * 8 + 2 * t;
            const float w0 = wk_s[cbase];
            const float w1 = wk_s[cbase + 1];
            float2 r0, r1;
            r0.x = SCALE * (C[mt][nt][0] - vo0 * w0);
            r0.y = SCALE * (C[mt][nt][1] - vo0 * w1);
            r1.x = SCALE * (C[mt][nt][2] - vo1 * w0);
            r1.y = SCALE * (C[mt][nt][3] - vo1 * w1);
            *(float2*)&o[(size_t)rbase * DH + cbase]       = r0;
            *(float2*)&o[(size_t)(rbase + 8) * DH + cbase] = r1;
        }
    }
}

// ---------------------------------------------------------------------------
extern "C" void kernel_launch(void* const* d_in, const int* in_sizes, int n_in,
                              void* d_out, int out_size) {
    const float* Q = (const float*)d_in[0];
    const float* K = (const float*)d_in[1];
    const float* V = (const float*)d_in[2];
    float* out = (float*)d_out;

    scores_kernel<<<dim3(32, BATCH), 256>>>(Q, K);
    softmax_kernel<<<BATCH * NQ, 256>>>();
    jac_kernel<<<BATCH * NQ, 128>>>(K, V, out);
}

// round 3
// speedup vs baseline: 4.2055x; 1.1976x over previous
#include <cuda_runtime.h>
#include <cuda_fp16.h>
#include <math.h>
#include <stdint.h>

#define BATCH 16
#define NQ    64
#define NSEQ  4096
#define DH    128
#define SCALE 0.08838834764831845f   // 1/sqrt(128)

// Scratch: attention weights a[b,q,n]. 16.7 MB.
__device__ float g_attn[(size_t)BATCH * NQ * NSEQ];

// ---------------------------------------------------------------------------
// Kernel 1: scores S[b,q,n] = (Q[b,q,:] . K[b,n,:]) * SCALE   (unchanged)
// ---------------------------------------------------------------------------
__global__ void scores_kernel(const float* __restrict__ Q,
                              const float* __restrict__ K) {
    __shared__ float Qs[64][33];
    __shared__ float Kt[128][33];

    const int b   = blockIdx.y;
    const int nt  = blockIdx.x;
    const int tid = threadIdx.x;
    const int ty  = tid >> 5;
    const int tx  = tid & 31;

    const float* Qb = Q + (size_t)b * NQ * DH;
    const float* Kb = K + ((size_t)b * NSEQ + (size_t)nt * 128) * DH;

    float acc[8][4];
    #pragma unroll
    for (int i = 0; i < 8; i++)
        #pragma unroll
        for (int j = 0; j < 4; j++) acc[i][j] = 0.f;

    for (int d0 = 0; d0 < DH; d0 += 32) {
        for (int i = tid; i < 64 * 32; i += 256) {
            int r = i >> 5, c = i & 31;
            Qs[r][c] = Qb[r * DH + d0 + c];
        }
        for (int i = tid; i < 128 * 32; i += 256) {
            int r = i >> 5, c = i & 31;
            Kt[r][c] = Kb[r * DH + d0 + c];
        }
        __syncthreads();

        #pragma unroll 8
        for (int dd = 0; dd < 32; dd++) {
            float qf[8], kf[4];
            #pragma unroll
            for (int i = 0; i < 8; i++) qf[i] = Qs[ty * 8 + i][dd];
            #pragma unroll
            for (int j = 0; j < 4; j++) kf[j] = Kt[tx * 4 + j][dd];
            #pragma unroll
            for (int i = 0; i < 8; i++)
                #pragma unroll
                for (int j = 0; j < 4; j++)
                    acc[i][j] += qf[i] * kf[j];
        }
        __syncthreads();
    }

    float* S = g_attn + ((size_t)b * NQ) * NSEQ + (size_t)nt * 128;
    #pragma unroll
    for (int i = 0; i < 8; i++)
        #pragma unroll
        for (int j = 0; j < 4; j++)
            S[(size_t)(ty * 8 + i) * NSEQ + tx * 4 + j] = acc[i][j] * SCALE;
}

// ---------------------------------------------------------------------------
// Kernel 2: in-place softmax over n per (b,q) row.   (unchanged)
// ---------------------------------------------------------------------------
__global__ void softmax_kernel() {
    const int row = blockIdx.x;
    float* p = g_attn + (size_t)row * NSEQ;
    const int tid = threadIdx.x;

    float v[16];
    float m = -1e30f;
    #pragma unroll
    for (int i = 0; i < 16; i++) {
        v[i] = p[tid + i * 256];
        m = fmaxf(m, v[i]);
    }

    __shared__ float red[256];
    red[tid] = m;
    __syncthreads();
    #pragma unroll
    for (int s = 128; s > 0; s >>= 1) {
        if (tid < s) red[tid] = fmaxf(red[tid], red[tid + s]);
        __syncthreads();
    }
    m = red[0];
    __syncthreads();

    float sum = 0.f;
    #pragma unroll
    for (int i = 0; i < 16; i++) {
        v[i] = __expf(v[i] - m);
        sum += v[i];
    }
    red[tid] = sum;
    __syncthreads();
    #pragma unroll
    for (int s = 128; s > 0; s >>= 1) {
        if (tid < s) red[tid] += red[tid + s];
        __syncthreads();
    }
    const float inv = 1.0f / red[0];
    #pragma unroll
    for (int i = 0; i < 16; i++) p[tid + i * 256] = v[i] * inv;
}

// ---------------------------------------------------------------------------
// Kernel 3 (fp16 tensor cores): per (b,q) CTA of 256 threads (8 warps, 2x4):
//   C[v,k]  = sum_n (a_n V[n,v]) K[n,k]   via mma.sync m16n8k16 f16 (fp32 acc)
//   vout[v] = sum_n a_n V[n,v] ; wk[k] = sum_n a_n K[n,k]  (exact fp32)
//   J       = SCALE * (C - vout (x) wk)
// smem tiles stored [n][feature] fp16, row stride 136 halves; A/B fragments
// gathered with ldmatrix.x4.trans (conflict-free: granule=(17*row+col/8)%8).
// ---------------------------------------------------------------------------
#define KC    32
#define SROW  136   // halves per smem row (128 + 8 pad)

__device__ __forceinline__ void mma_f16(float c[4], uint32_t a0, uint32_t a1,
                                        uint32_t a2, uint32_t a3,
                                        uint32_t b0, uint32_t b1) {
    asm volatile(
        "mma.sync.aligned.m16n8k16.row.col.f32.f16.f16.f32 "
        "{%0,%1,%2,%3}, {%4,%5,%6,%7}, {%8,%9}, {%0,%1,%2,%3};"
        : "+f"(c[0]), "+f"(c[1]), "+f"(c[2]), "+f"(c[3])
        : "r"(a0), "r"(a1), "r"(a2), "r"(a3), "r"(b0), "r"(b1));
}

__device__ __forceinline__ void ldsm4t(uint32_t& r0, uint32_t& r1,
                                       uint32_t& r2, uint32_t& r3, uint32_t addr) {
    asm volatile(
        "ldmatrix.sync.aligned.m8n8.x4.trans.shared.b16 {%0,%1,%2,%3}, [%4];"
        : "=r"(r0), "=r"(r1), "=r"(r2), "=r"(r3) : "r"(addr));
}

__global__ __launch_bounds__(256, 2) void jac_kernel(const float* __restrict__ K,
                                                     const float* __restrict__ V,
                                                     float* __restrict__ out) {
    __shared__ __half avs[KC * SROW];   // a_n * V[n][v]  (fp16)
    __shared__ __half kss[KC * SROW];   // K[n][k]        (fp16)
    __shared__ float vred[8][128];
    __shared__ float kred[8][128];
    __shared__ float vout_s[128];
    __shared__ float wk_s[128];

    const int bq = blockIdx.x;
    const int b  = bq >> 6;
    const float* a  = g_attn + (size_t)bq * NSEQ;
    const float* Kb = K + (size_t)b * NSEQ * DH;
    const float* Vb = V + (size_t)b * NSEQ * DH;

    const int tid  = threadIdx.x;
    const int warp = tid >> 5;
    const int lane = tid & 31;
    const int g    = lane >> 2;
    const int t    = lane & 3;
    const int wm   = warp >> 2;   // 0..1  -> 64 v-rows
    const int wn   = warp & 3;    // 0..3  -> 32 k-cols

    // ldmatrix.trans per-lane offsets (in elements)
    const int lj = lane & 7;
    const int ls = lane >> 3;
    const int a_ro = lj + ((ls >> 1) << 3);   // row offset (n) for A
    const int a_co = (ls & 1) << 3;           // col offset (v) for A
    const int b_ro = lj + ((ls & 1) << 3);    // row offset (n) for B
    const int b_co = (ls >> 1) << 3;          // col offset (k) for B

    const uint32_t avs_base = (uint32_t)__cvta_generic_to_shared(avs);
    const uint32_t kss_base = (uint32_t)__cvta_generic_to_shared(kss);

    float C[4][4][4];
    #pragma unroll
    for (int mt = 0; mt < 4; mt++)
        #pragma unroll
        for (int nt = 0; nt < 4; nt++)
            #pragma unroll
            for (int r = 0; r < 4; r++) C[mt][nt][r] = 0.f;

    float vout4[4] = {0.f, 0.f, 0.f, 0.f};
    float wk4[4]   = {0.f, 0.f, 0.f, 0.f};

    for (int n0 = 0; n0 < NSEQ; n0 += KC) {
        // ---- load + a-scale + fp16 convert; exact fp32 vout/wk partials
        const float4* Vg = (const float4*)(Vb + (size_t)n0 * DH);
        const float4* Kg = (const float4*)(Kb + (size_t)n0 * DH);
        #pragma unroll
        for (int i = 0; i < 4; i++) {
            const int row = warp + 8 * i;            // 0..31
            const float av = __ldg(a + n0 + row);    // warp-broadcast
            float4 v4 = Vg[row * 32 + lane];
            float4 k4 = Kg[row * 32 + lane];
            float avx = av * v4.x, avy = av * v4.y, avz = av * v4.z, avw = av * v4.w;
            vout4[0] += avx; vout4[1] += avy; vout4[2] += avz; vout4[3] += avw;
            wk4[0] += av * k4.x; wk4[1] += av * k4.y;
            wk4[2] += av * k4.z; wk4[3] += av * k4.w;
            __half2 h0 = __floats2half2_rn(avx, avy);
            __half2 h1 = __floats2half2_rn(avz, avw);
            __half2 p0 = __floats2half2_rn(k4.x, k4.y);
            __half2 p1 = __floats2half2_rn(k4.z, k4.w);
            *(__half2*)&avs[row * SROW + lane * 4]     = h0;
            *(__half2*)&avs[row * SROW + lane * 4 + 2] = h1;
            *(__half2*)&kss[row * SROW + lane * 4]     = p0;
            *(__half2*)&kss[row * SROW + lane * 4 + 2] = p1;
        }
        __syncthreads();

        // ---- 2 ksteps of 16 over this chunk
        #pragma unroll
        for (int ks = 0; ks < 2; ks++) {
            const int k0 = ks * 16;
            uint32_t bf[4][2];
            #pragma unroll
            for (int pair = 0; pair < 2; pair++) {
                const int c0 = wn * 32 + pair * 16;
                uint32_t addr = kss_base +
                    ((k0 + b_ro) * SROW + c0 + b_co) * 2;
                ldsm4t(bf[2 * pair][0], bf[2 * pair][1],
                       bf[2 * pair + 1][0], bf[2 * pair + 1][1], addr);
            }
            #pragma unroll
            for (int mt = 0; mt < 4; mt++) {
                const int m0 = wm * 64 + mt * 16;
                uint32_t a0, a1, a2, a3;
                uint32_t addr = avs_base +
                    ((k0 + a_ro) * SROW + m0 + a_co) * 2;
                ldsm4t(a0, a1, a2, a3, addr);
                #pragma unroll
                for (int nt = 0; nt < 4; nt++)
                    mma_f16(C[mt][nt], a0, a1, a2, a3, bf[nt][0], bf[nt][1]);
            }
        }
        __syncthreads();
    }

    // ---- reduce vout/wk partials across 8 warps
    #pragma unroll
    for (int jv = 0; jv < 4; jv++) {
        vred[warp][lane * 4 + jv] = vout4[jv];
        kred[warp][lane * 4 + jv] = wk4[jv];
    }
    __syncthreads();
    if (tid < 128) {
        float s = 0.f;
        #pragma unroll
        for (int w = 0; w < 8; w++) s += vred[w][tid];
        vout_s[tid] = s;
    } else {
        const int c = tid - 128;
        float s = 0.f;
        #pragma unroll
        for (int w = 0; w < 8; w++) s += kred[w][c];
        wk_s[c] = s;
    }
    __syncthreads();

    // ---- epilogue: J = SCALE * (C - vout (x) wk)
    float* o = out + (size_t)bq * DH * DH;
    #pragma unroll
    for (int mt = 0; mt < 4; mt++) {
        const int rbase = wm * 64 + mt * 16 + g;
        const float vo0 = vout_s[rbase];
        const float vo1 = vout_s[rbase + 8];
        #pragma unroll
        for (int nt = 0; nt < 4; nt++) {
            const int cbase = wn * 32 + nt * 8 + 2 * t;
            const float w0 = wk_s[cbase];
            const float w1 = wk_s[cbase + 1];
            float2 r0, r1;
            r0.x = SCALE * (C[mt][nt][0] - vo0 * w0);
            r0.y = SCALE * (C[mt][nt][1] - vo0 * w1);
            r1.x = SCALE * (C[mt][nt][2] - vo1 * w0);
            r1.y = SCALE * (C[mt][nt][3] - vo1 * w1);
            *(float2*)&o[(size_t)rbase * DH + cbase]       = r0;
            *(float2*)&o[(size_t)(rbase + 8) * DH + cbase] = r1;
        }
    }
}

// ---------------------------------------------------------------------------
extern "C" void kernel_launch(void* const* d_in, const int* in_sizes, int n_in,
                              void* d_out, int out_size) {
    const float* Q = (const float*)d_in[0];
    const float* K = (const float*)d_in[1];
    const float* V = (const float*)d_in[2];
    float* out = (float*)d_out;

    scores_kernel<<<dim3(32, BATCH), 256>>>(Q, K);
    softmax_kernel<<<BATCH * NQ, 256>>>();
    jac_kernel<<<BATCH * NQ, 256>>>(K, V, out);
}

// round 4
// speedup vs baseline: 4.2908x; 1.0203x over previous
#include <cuda_runtime.h>
#include <cuda_fp16.h>
#include <math.h>
#include <stdint.h>

#define BATCH 16
#define NQ    64
#define NSEQ  4096
#define DH    128
#define SCALE 0.08838834764831845f   // 1/sqrt(128)

// Scratch
__device__ float g_attn[(size_t)BATCH * NQ * NSEQ];   // softmax weights
__device__ float g_vout[(size_t)BATCH * NQ * DH];     // sum_n a V  (exact fp32)
__device__ float g_wk  [(size_t)BATCH * NQ * DH];     // sum_n a K  (exact fp32)

// ---------------------------------------------------------------------------
// Kernel 1: scores S[b,q,n] = (Q[b,q,:] . K[b,n,:]) * SCALE
// ---------------------------------------------------------------------------
__global__ void scores_kernel(const float* __restrict__ Q,
                              const float* __restrict__ K) {
    __shared__ float Qs[64][33];
    __shared__ float Kt[128][33];

    const int b   = blockIdx.y;
    const int nt  = blockIdx.x;
    const int tid = threadIdx.x;
    const int ty  = tid >> 5;
    const int tx  = tid & 31;

    const float* Qb = Q + (size_t)b * NQ * DH;
    const float* Kb = K + ((size_t)b * NSEQ + (size_t)nt * 128) * DH;

    float acc[8][4];
    #pragma unroll
    for (int i = 0; i < 8; i++)
        #pragma unroll
        for (int j = 0; j < 4; j++) acc[i][j] = 0.f;

    for (int d0 = 0; d0 < DH; d0 += 32) {
        for (int i = tid; i < 64 * 32; i += 256) {
            int r = i >> 5, c = i & 31;
            Qs[r][c] = Qb[r * DH + d0 + c];
        }
        for (int i = tid; i < 128 * 32; i += 256) {
            int r = i >> 5, c = i & 31;
            Kt[r][c] = Kb[r * DH + d0 + c];
        }
        __syncthreads();

        #pragma unroll 8
        for (int dd = 0; dd < 32; dd++) {
            float qf[8], kf[4];
            #pragma unroll
            for (int i = 0; i < 8; i++) qf[i] = Qs[ty * 8 + i][dd];
            #pragma unroll
            for (int j = 0; j < 4; j++) kf[j] = Kt[tx * 4 + j][dd];
            #pragma unroll
            for (int i = 0; i < 8; i++)
                #pragma unroll
                for (int j = 0; j < 4; j++)
                    acc[i][j] += qf[i] * kf[j];
        }
        __syncthreads();
    }

    float* S = g_attn + ((size_t)b * NQ) * NSEQ + (size_t)nt * 128;
    #pragma unroll
    for (int i = 0; i < 8; i++)
        #pragma unroll
        for (int j = 0; j < 4; j++)
            S[(size_t)(ty * 8 + i) * NSEQ + tx * 4 + j] = acc[i][j] * SCALE;
}

// ---------------------------------------------------------------------------
// Kernel 2: in-place softmax over n per (b,q) row.
// ---------------------------------------------------------------------------
__global__ void softmax_kernel() {
    const int row = blockIdx.x;
    float* p = g_attn + (size_t)row * NSEQ;
    const int tid = threadIdx.x;

    float v[16];
    float m = -1e30f;
    #pragma unroll
    for (int i = 0; i < 16; i++) {
        v[i] = p[tid + i * 256];
        m = fmaxf(m, v[i]);
    }

    __shared__ float red[256];
    red[tid] = m;
    __syncthreads();
    #pragma unroll
    for (int s = 128; s > 0; s >>= 1) {
        if (tid < s) red[tid] = fmaxf(red[tid], red[tid + s]);
        __syncthreads();
    }
    m = red[0];
    __syncthreads();

    float sum = 0.f;
    #pragma unroll
    for (int i = 0; i < 16; i++) {
        v[i] = __expf(v[i] - m);
        sum += v[i];
    }
    red[tid] = sum;
    __syncthreads();
    #pragma unroll
    for (int s = 128; s > 0; s >>= 1) {
        if (tid < s) red[tid] += red[tid + s];
        __syncthreads();
    }
    const float inv = 1.0f / red[0];
    #pragma unroll
    for (int i = 0; i < 16; i++) p[tid + i * 256] = v[i] * inv;
}

// ---------------------------------------------------------------------------
// Kernel 3: aux — exact fp32 vout[bq][:] = a.V, wk[bq][:] = a.K.
// grid 256 = (b:16, mat:2, qg:8). CTA computes 8 q-rows x 128 cols.
// ---------------------------------------------------------------------------
__global__ __launch_bounds__(256) void aux_kernel(const float* __restrict__ K,
                                                  const float* __restrict__ V) {
    __shared__ float Ms[64 * 128];   // 32KB
    __shared__ float As[8 * 64];

    const int bid = blockIdx.x;
    const int b   = bid >> 4;
    const int rm  = bid & 15;
    const int mat = rm >> 3;
    const int qg  = rm & 7;
    const int bq0 = b * NQ + qg * 8;

    const float* M  = (mat ? K : V) + (size_t)b * NSEQ * DH;
    const float* aA = g_attn + (size_t)bq0 * NSEQ;

    const int tid  = threadIdx.x;
    const int ccol = tid & 127;
    const int qh   = tid >> 7;   // 0..1 -> 4 q's each

    float acc[4] = {0.f, 0.f, 0.f, 0.f};

    for (int n0 = 0; n0 < NSEQ; n0 += 64) {
        const float4* Mg  = (const float4*)(M + (size_t)n0 * DH);
        float4*       Ms4 = (float4*)Ms;
        #pragma unroll
        for (int i = 0; i < 8; i++) Ms4[tid + i * 256] = Mg[tid + i * 256];
        #pragma unroll
        for (int i = 0; i < 2; i++) {
            int idx = tid + i * 256;
            int q = idx >> 6, n = idx & 63;
            As[idx] = aA[(size_t)q * NSEQ + n0 + n];
        }
        __syncthreads();

        #pragma unroll 4
        for (int n = 0; n < 64; n++) {
            float mv = Ms[n * 128 + ccol];
            #pragma unroll
            for (int i = 0; i < 4; i++)
                acc[i] += As[(qh * 4 + i) * 64 + n] * mv;
        }
        __syncthreads();
    }

    float* dst = mat ? g_wk : g_vout;
    #pragma unroll
    for (int i = 0; i < 4; i++)
        dst[(size_t)(bq0 + qh * 4 + i) * DH + ccol] = acc[i];
}

// ---------------------------------------------------------------------------
// Kernel 4: jac — per CTA (8 q, 64 v, 32 k), 256 threads / 8 warps.
//   C_q[v,k] = sum_n (a_qn V[n,v]) K[n,k]   (fp16 MMA, fp32 acc)
//   J_q      = SCALE * (C_q - vout_q (x) wk_q)
// ---------------------------------------------------------------------------
#define KC     32
#define AVS    72    // halves per aV row  (64 + 8 pad)
#define KSS    40    // halves per K row   (32 + 8 pad)

__device__ __forceinline__ void mma_f16(float c[4], uint32_t a0, uint32_t a1,
                                        uint32_t a2, uint32_t a3,
                                        uint32_t b0, uint32_t b1) {
    asm volatile(
        "mma.sync.aligned.m16n8k16.row.col.f32.f16.f16.f32 "
        "{%0,%1,%2,%3}, {%4,%5,%6,%7}, {%8,%9}, {%0,%1,%2,%3};"
        : "+f"(c[0]), "+f"(c[1]), "+f"(c[2]), "+f"(c[3])
        : "r"(a0), "r"(a1), "r"(a2), "r"(a3), "r"(b0), "r"(b1));
}

__device__ __forceinline__ void ldsm4t(uint32_t& r0, uint32_t& r1,
                                       uint32_t& r2, uint32_t& r3, uint32_t addr) {
    asm volatile(
        "ldmatrix.sync.aligned.m8n8.x4.trans.shared.b16 {%0,%1,%2,%3}, [%4];"
        : "=r"(r0), "=r"(r1), "=r"(r2), "=r"(r3) : "r"(addr));
}

__global__ __launch_bounds__(256, 2) void jac_kernel(const float* __restrict__ K,
                                                     const float* __restrict__ V,
                                                     float* __restrict__ out) {
    __shared__ __half avs[8][KC * AVS];   // 36864 B
    __shared__ __half kss[KC * KSS];      //  2560 B

    const int bid = blockIdx.x;           // 1024 CTAs
    const int b   = bid >> 6;
    const int r   = bid & 63;
    const int qg  = r >> 3;               // 0..7
    const int kq  = (r >> 1) & 3;         // 0..3 -> 32 k-cols
    const int vh  = r & 1;                // 0..1 -> 64 v-cols
    const int v0  = vh * 64;
    const int k0g = kq * 32;
    const int bq0 = b * NQ + qg * 8;

    const float* aA = g_attn + (size_t)bq0 * NSEQ;
    const float* Vb = V + (size_t)b * NSEQ * DH + v0;
    const float* Kb = K + (size_t)b * NSEQ * DH + k0g;

    const int tid  = threadIdx.x;
    const int warp = tid >> 5;
    const int lane = tid & 31;

    // load-phase indices
    const int na  = tid >> 4;     // 0..15 (V rows na, na+16)
    const int c4  = tid & 15;     // V float4 col
    const int nk  = tid >> 3;     // 0..31 (K row)
    const int c4k = tid & 7;      // K float4 col

    // mma-phase indices
    const int g  = lane >> 2;
    const int t  = lane & 3;
    const int lj = lane & 7;
    const int ls = lane >> 3;
    const int wm = warp >> 1;     // 0..3 -> m0 = wm*16
    const int wn = warp & 1;      // 0..1 -> n0c = wn*16
    const int m0  = wm * 16;
    const int n0c = wn * 16;

    const uint32_t avs_base = (uint32_t)__cvta_generic_to_shared(avs);
    const uint32_t kss_base = (uint32_t)__cvta_generic_to_shared(kss);
    const uint32_t a_lane = ((lj + ((ls >> 1) << 3)) * AVS + m0 + ((ls & 1) << 3)) * 2;
    const uint32_t b_lane = ((lj + ((ls & 1) << 3)) * KSS + n0c + ((ls >> 1) << 3)) * 2;

    float C[8][2][4];
    #pragma unroll
    for (int q = 0; q < 8; q++)
        #pragma unroll
        for (int nt = 0; nt < 2; nt++)
            #pragma unroll
            for (int i = 0; i < 4; i++) C[q][nt][i] = 0.f;

    // prologue: chunk 0
    float4 va  = *(const float4*)(Vb + (size_t)na * DH + c4 * 4);
    float4 vb2 = *(const float4*)(Vb + (size_t)(na + 16) * DH + c4 * 4);
    float4 kk  = *(const float4*)(Kb + (size_t)nk * DH + c4k * 4);
    float ar[16];
    #pragma unroll
    for (int q = 0; q < 8; q++) {
        ar[2 * q]     = aA[(size_t)q * NSEQ + na];
        ar[2 * q + 1] = aA[(size_t)q * NSEQ + na + 16];
    }

    for (int c = 0; c < NSEQ / KC; c++) {
        // ---- write tiles from current regs
        {
            __half2 p0 = __floats2half2_rn(kk.x, kk.y);
            __half2 p1 = __floats2half2_rn(kk.z, kk.w);
            uint2 pk;
            pk.x = *(uint32_t*)&p0; pk.y = *(uint32_t*)&p1;
            *(uint2*)&kss[nk * KSS + c4k * 4] = pk;
        }
        #pragma unroll
        for (int q = 0; q < 8; q++) {
            const float a0 = ar[2 * q], a1 = ar[2 * q + 1];
            __half2 h0 = __floats2half2_rn(a0 * va.x,  a0 * va.y);
            __half2 h1 = __floats2half2_rn(a0 * va.z,  a0 * va.w);
            __half2 h2 = __floats2half2_rn(a1 * vb2.x, a1 * vb2.y);
            __half2 h3 = __floats2half2_rn(a1 * vb2.z, a1 * vb2.w);
            uint2 u0, u1;
            u0.x = *(uint32_t*)&h0; u0.y = *(uint32_t*)&h1;
            u1.x = *(uint32_t*)&h2; u1.y = *(uint32_t*)&h3;
            *(uint2*)&avs[q][na * AVS + c4 * 4]        = u0;
            *(uint2*)&avs[q][(na + 16) * AVS + c4 * 4] = u1;
        }
        __syncthreads();   // tiles ready

        // ---- prefetch next chunk into regs (overlaps with MMA)
        float4 nva, nvb, nkk;
        float nar[16];
        if (c + 1 < NSEQ / KC) {
            const size_t nn = (size_t)(c + 1) * KC;
            nva = *(const float4*)(Vb + (nn + na) * DH + c4 * 4);
            nvb = *(const float4*)(Vb + (nn + na + 16) * DH + c4 * 4);
            nkk = *(const float4*)(Kb + (nn + nk) * DH + c4k * 4);
            #pragma unroll
            for (int q = 0; q < 8; q++) {
                nar[2 * q]     = aA[(size_t)q * NSEQ + nn + na];
                nar[2 * q + 1] = aA[(size_t)q * NSEQ + nn + na + 16];
            }
        }

        // ---- MMA: 2 ksteps of 16
        #pragma unroll
        for (int ks = 0; ks < 2; ks++) {
            uint32_t b0, b1, b2, b3;
            ldsm4t(b0, b1, b2, b3,
                   kss_base + b_lane + ks * (16 * KSS * 2));
            #pragma unroll
            for (int q = 0; q < 8; q++) {
                uint32_t a0, a1, a2, a3;
                ldsm4t(a0, a1, a2, a3,
                       avs_base + q * (KC * AVS * 2) + a_lane + ks * (16 * AVS * 2));
                mma_f16(C[q][0], a0, a1, a2, a3, b0, b1);
                mma_f16(C[q][1], a0, a1, a2, a3, b2, b3);
            }
        }

        va = nva; vb2 = nvb; kk = nkk;
        #pragma unroll
        for (int i = 0; i < 16; i++) ar[i] = nar[i];
        __syncthreads();   // MMA reads done before next writes
    }

    // ---- epilogue: J = SCALE * (C - vout (x) wk)
    #pragma unroll
    for (int q = 0; q < 8; q++) {
        const int bq = bq0 + q;
        const float* vo = g_vout + (size_t)bq * DH + v0;
        const float* wq = g_wk   + (size_t)bq * DH + k0g;
        float* o = out + (size_t)bq * DH * DH;
        const float vo0 = vo[m0 + g];
        const float vo1 = vo[m0 + g + 8];
        #pragma unroll
        for (int nt = 0; nt < 2; nt++) {
            const int col = n0c + nt * 8 + 2 * t;
            const float w0 = wq[col];
            const float w1 = wq[col + 1];
            float2 r0, r1;
            r0.x = SCALE * (C[q][nt][0] - vo0 * w0);
            r0.y = SCALE * (C[q][nt][1] - vo0 * w1);
            r1.x = SCALE * (C[q][nt][2] - vo1 * w0);
            r1.y = SCALE * (C[q][nt][3] - vo1 * w1);
            *(float2*)&o[(size_t)(v0 + m0 + g) * DH + k0g + col]     = r0;
            *(float2*)&o[(size_t)(v0 + m0 + g + 8) * DH + k0g + col] = r1;
        }
    }
}

// ---------------------------------------------------------------------------
extern "C" void kernel_launch(void* const* d_in, const int* in_sizes, int n_in,
                              void* d_out, int out_size) {
    const float* Q = (const float*)d_in[0];
    const float* K = (const float*)d_in[1];
    const float* V = (const float*)d_in[2];
    float* out = (float*)d_out;

    scores_kernel<<<dim3(32, BATCH), 256>>>(Q, K);
    softmax_kernel<<<BATCH * NQ, 256>>>();
    aux_kernel<<<256, 256>>>(K, V);
    jac_kernel<<<BATCH * NQ, 256>>>(K, V, out);
}

// round 5
// speedup vs baseline: 4.5984x; 1.0717x over previous
#include <cuda_runtime.h>
#include <cuda_fp16.h>
#include <math.h>
#include <stdint.h>

#define BATCH 16
#define NQ    64
#define NSEQ  4096
#define DH    128
#define SCALE 0.08838834764831845f   // 1/sqrt(128)

// Scratch
__device__ float g_attn[(size_t)BATCH * NQ * NSEQ];   // softmax weights
__device__ float g_vout[(size_t)BATCH * NQ * DH];     // sum_n a V  (exact fp32)
__device__ float g_wk  [(size_t)BATCH * NQ * DH];     // sum_n a K  (exact fp32)

// ---------------------------------------------------------------------------
// Kernel 1: scores S[b,q,n] = (Q[b,q,:] . K[b,n,:]) * SCALE
// ---------------------------------------------------------------------------
__global__ void scores_kernel(const float* __restrict__ Q,
                              const float* __restrict__ K) {
    __shared__ float Qs[64][33];
    __shared__ float Kt[128][33];

    const int b   = blockIdx.y;
    const int nt  = blockIdx.x;
    const int tid = threadIdx.x;
    const int ty  = tid >> 5;
    const int tx  = tid & 31;

    const float* Qb = Q + (size_t)b * NQ * DH;
    const float* Kb = K + ((size_t)b * NSEQ + (size_t)nt * 128) * DH;

    float acc[8][4];
    #pragma unroll
    for (int i = 0; i < 8; i++)
        #pragma unroll
        for (int j = 0; j < 4; j++) acc[i][j] = 0.f;

    for (int d0 = 0; d0 < DH; d0 += 32) {
        for (int i = tid; i < 64 * 32; i += 256) {
            int r = i >> 5, c = i & 31;
            Qs[r][c] = Qb[r * DH + d0 + c];
        }
        for (int i = tid; i < 128 * 32; i += 256) {
            int r = i >> 5, c = i & 31;
            Kt[r][c] = Kb[r * DH + d0 + c];
        }
        __syncthreads();

        #pragma unroll 8
        for (int dd = 0; dd < 32; dd++) {
            float qf[8], kf[4];
            #pragma unroll
            for (int i = 0; i < 8; i++) qf[i] = Qs[ty * 8 + i][dd];
            #pragma unroll
            for (int j = 0; j < 4; j++) kf[j] = Kt[tx * 4 + j][dd];
            #pragma unroll
            for (int i = 0; i < 8; i++)
                #pragma unroll
                for (int j = 0; j < 4; j++)
                    acc[i][j] += qf[i] * kf[j];
        }
        __syncthreads();
    }

    float* S = g_attn + ((size_t)b * NQ) * NSEQ + (size_t)nt * 128;
    #pragma unroll
    for (int i = 0; i < 8; i++)
        #pragma unroll
        for (int j = 0; j < 4; j++)
            S[(size_t)(ty * 8 + i) * NSEQ + tx * 4 + j] = acc[i][j] * SCALE;
}

// ---------------------------------------------------------------------------
// Kernel 2: in-place softmax over n per (b,q) row.
// ---------------------------------------------------------------------------
__global__ void softmax_kernel() {
    const int row = blockIdx.x;
    float* p = g_attn + (size_t)row * NSEQ;
    const int tid = threadIdx.x;

    float v[16];
    float m = -1e30f;
    #pragma unroll
    for (int i = 0; i < 16; i++) {
        v[i] = p[tid + i * 256];
        m = fmaxf(m, v[i]);
    }

    __shared__ float red[256];
    red[tid] = m;
    __syncthreads();
    #pragma unroll
    for (int s = 128; s > 0; s >>= 1) {
        if (tid < s) red[tid] = fmaxf(red[tid], red[tid + s]);
        __syncthreads();
    }
    m = red[0];
    __syncthreads();

    float sum = 0.f;
    #pragma unroll
    for (int i = 0; i < 16; i++) {
        v[i] = __expf(v[i] - m);
        sum += v[i];
    }
    red[tid] = sum;
    __syncthreads();
    #pragma unroll
    for (int s = 128; s > 0; s >>= 1) {
        if (tid < s) red[tid] += red[tid + s];
        __syncthreads();
    }
    const float inv = 1.0f / red[0];
    #pragma unroll
    for (int i = 0; i < 16; i++) p[tid + i * 256] = v[i] * inv;
}

// ---------------------------------------------------------------------------
// Kernel 3: aux — exact fp32 vout[bq][:] = a.V, wk[bq][:] = a.K.
// grid 256 = (b:16, mat:2, qg:8). CTA computes 8 q-rows x 128 cols.
// ---------------------------------------------------------------------------
__global__ __launch_bounds__(256) void aux_kernel(const float* __restrict__ K,
                                                  const float* __restrict__ V) {
    __shared__ float Ms[64 * 128];   // 32KB
    __shared__ float As[8 * 64];

    const int bid = blockIdx.x;
    const int b   = bid >> 4;
    const int rm  = bid & 15;
    const int mat = rm >> 3;
    const int qg  = rm & 7;
    const int bq0 = b * NQ + qg * 8;

    const float* M  = (mat ? K : V) + (size_t)b * NSEQ * DH;
    const float* aA = g_attn + (size_t)bq0 * NSEQ;

    const int tid  = threadIdx.x;
    const int ccol = tid & 127;
    const int qh   = tid >> 7;   // 0..1 -> 4 q's each

    float acc[4] = {0.f, 0.f, 0.f, 0.f};

    for (int n0 = 0; n0 < NSEQ; n0 += 64) {
        const float4* Mg  = (const float4*)(M + (size_t)n0 * DH);
        float4*       Ms4 = (float4*)Ms;
        #pragma unroll
        for (int i = 0; i < 8; i++) Ms4[tid + i * 256] = Mg[tid + i * 256];
        #pragma unroll
        for (int i = 0; i < 2; i++) {
            int idx = tid + i * 256;
            int q = idx >> 6, n = idx & 63;
            As[idx] = aA[(size_t)q * NSEQ + n0 + n];
        }
        __syncthreads();

        #pragma unroll 4
        for (int n = 0; n < 64; n++) {
            float mv = Ms[n * 128 + ccol];
            #pragma unroll
            for (int i = 0; i < 4; i++)
                acc[i] += As[(qh * 4 + i) * 64 + n] * mv;
        }
        __syncthreads();
    }

    float* dst = mat ? g_wk : g_vout;
    #pragma unroll
    for (int i = 0; i < 4; i++)
        dst[(size_t)(bq0 + qh * 4 + i) * DH + ccol] = acc[i];
}

// ---------------------------------------------------------------------------
// Kernel 4: jac — per CTA (4 q, 64 v, 128 k), 256 threads / 8 warps (4wm x 2wn).
//   C_q[v,k] = sum_n (a_qn V[n,v]) K[n,k]   (fp16 MMA, fp32 acc)
//   J_q      = SCALE * (C_q - vout_q (x) wk_q)
// K tile converted once per chunk and shared by all 4 queries.
// ---------------------------------------------------------------------------
#define KC     32
#define AVS    72    // halves per aV row  (64 + 8 pad)
#define KSS    136   // halves per K row   (128 + 8 pad)

__device__ __forceinline__ void mma_f16(float c[4], uint32_t a0, uint32_t a1,
                                        uint32_t a2, uint32_t a3,
                                        uint32_t b0, uint32_t b1) {
    asm volatile(
        "mma.sync.aligned.m16n8k16.row.col.f32.f16.f16.f32 "
        "{%0,%1,%2,%3}, {%4,%5,%6,%7}, {%8,%9}, {%0,%1,%2,%3};"
        : "+f"(c[0]), "+f"(c[1]), "+f"(c[2]), "+f"(c[3])
        : "r"(a0), "r"(a1), "r"(a2), "r"(a3), "r"(b0), "r"(b1));
}

__device__ __forceinline__ void ldsm4t(uint32_t& r0, uint32_t& r1,
                                       uint32_t& r2, uint32_t& r3, uint32_t addr) {
    asm volatile(
        "ldmatrix.sync.aligned.m8n8.x4.trans.shared.b16 {%0,%1,%2,%3}, [%4];"
        : "=r"(r0), "=r"(r1), "=r"(r2), "=r"(r3) : "r"(addr));
}

__global__ __launch_bounds__(256, 1) void jac_kernel(const float* __restrict__ K,
                                                     const float* __restrict__ V,
                                                     float* __restrict__ out) {
    __shared__ __half avs[4][KC * AVS];   // 18432 B
    __shared__ __half kss[KC * KSS];      //  8704 B

    const int bid = blockIdx.x;           // 512 CTAs
    const int b   = bid >> 5;
    const int r   = bid & 31;
    const int qg  = r >> 1;               // 0..15 -> 4 q's
    const int vh  = r & 1;                // 0..1  -> 64 v-cols
    const int v0  = vh * 64;
    const int bq0 = b * NQ + qg * 4;

    const float* aA = g_attn + (size_t)bq0 * NSEQ;
    const float* Vb = V + (size_t)b * NSEQ * DH + v0;
    const float* Kb = K + (size_t)b * NSEQ * DH;

    const int tid  = threadIdx.x;
    const int warp = tid >> 5;
    const int lane = tid & 31;

    // load-phase indices
    const int rowV  = tid >> 4;    // V rows rowV, rowV+16 ; f4 col colV4
    const int colV4 = tid & 15;
    const int rowK  = tid >> 5;    // K rows rowK + 8i     ; f4 col colK4
    const int colK4 = tid & 31;

    // mma-phase indices
    const int g  = lane >> 2;
    const int t  = lane & 3;
    const int lj = lane & 7;
    const int ls = lane >> 3;
    const int wm = warp >> 1;      // 0..3 -> m0 = wm*16 (of 64 v)
    const int wn = warp & 1;       // 0..1 -> k cols wn*64..+64
    const int m0 = wm * 16;

    const uint32_t avs_base = (uint32_t)__cvta_generic_to_shared(avs);
    const uint32_t kss_base = (uint32_t)__cvta_generic_to_shared(kss);
    const uint32_t a_lane =
        (uint32_t)(((lj + ((ls >> 1) << 3)) * AVS + m0 + ((ls & 1) << 3)) * 2);
    const uint32_t b_lane =
        (uint32_t)(((lj + ((ls & 1) << 3)) * KSS + wn * 64 + ((ls >> 1) << 3)) * 2);

    float C[4][8][4];
    #pragma unroll
    for (int q = 0; q < 4; q++)
        #pragma unroll
        for (int nt = 0; nt < 8; nt++)
            #pragma unroll
            for (int i = 0; i < 4; i++) C[q][nt][i] = 0.f;

    // prologue: chunk 0 into regs
    float4 va[2], kk[4];
    float  ar[4][2];
    #pragma unroll
    for (int i = 0; i < 2; i++)
        va[i] = *(const float4*)(Vb + (size_t)(rowV + 16 * i) * DH + colV4 * 4);
    #pragma unroll
    for (int i = 0; i < 4; i++)
        kk[i] = *(const float4*)(Kb + (size_t)(rowK + 8 * i) * DH + colK4 * 4);
    #pragma unroll
    for (int q = 0; q < 4; q++)
        #pragma unroll
        for (int i = 0; i < 2; i++)
            ar[q][i] = aA[(size_t)q * NSEQ + rowV + 16 * i];

    for (int c = 0; c < NSEQ / KC; c++) {
        // ---- build tiles from current regs
        #pragma unroll
        for (int i = 0; i < 4; i++) {
            __half2 p0 = __floats2half2_rn(kk[i].x, kk[i].y);
            __half2 p1 = __floats2half2_rn(kk[i].z, kk[i].w);
            uint2 pk;
            pk.x = *(uint32_t*)&p0; pk.y = *(uint32_t*)&p1;
            *(uint2*)&kss[(rowK + 8 * i) * KSS + colK4 * 4] = pk;
        }
        #pragma unroll
        for (int q = 0; q < 4; q++) {
            #pragma unroll
            for (int i = 0; i < 2; i++) {
                const float aq = ar[q][i];
                __half2 h0 = __floats2half2_rn(aq * va[i].x, aq * va[i].y);
                __half2 h1 = __floats2half2_rn(aq * va[i].z, aq * va[i].w);
                uint2 u;
                u.x = *(uint32_t*)&h0; u.y = *(uint32_t*)&h1;
                *(uint2*)&avs[q][(rowV + 16 * i) * AVS + colV4 * 4] = u;
            }
        }
        __syncthreads();   // tiles ready

        // ---- prefetch next chunk into regs (overlaps with MMA)
        float4 nva[2], nkk[4];
        float  nar[4][2];
        if (c + 1 < NSEQ / KC) {
            const size_t nn = (size_t)(c + 1) * KC;
            #pragma unroll
            for (int i = 0; i < 2; i++)
                nva[i] = *(const float4*)(Vb + (nn + rowV + 16 * i) * DH + colV4 * 4);
            #pragma unroll
            for (int i = 0; i < 4; i++)
                nkk[i] = *(const float4*)(Kb + (nn + rowK + 8 * i) * DH + colK4 * 4);
            #pragma unroll
            for (int q = 0; q < 4; q++)
                #pragma unroll
                for (int i = 0; i < 2; i++)
                    nar[q][i] = aA[(size_t)q * NSEQ + nn + rowV + 16 * i];
        }

        // ---- MMA: 2 ksteps of 16
        #pragma unroll
        for (int ks = 0; ks < 2; ks++) {
            uint32_t bf[8][2];
            #pragma unroll
            for (int p = 0; p < 4; p++) {
                ldsm4t(bf[2 * p][0], bf[2 * p][1],
                       bf[2 * p + 1][0], bf[2 * p + 1][1],
                       kss_base + b_lane + p * 32 + ks * (16 * KSS * 2));
            }
            #pragma unroll
            for (int q = 0; q < 4; q++) {
                uint32_t a0, a1, a2, a3;
                ldsm4t(a0, a1, a2, a3,
                       avs_base + q * (KC * AVS * 2) + a_lane + ks * (16 * AVS * 2));
                #pragma unroll
                for (int nt = 0; nt < 8; nt++)
                    mma_f16(C[q][nt], a0, a1, a2, a3, bf[nt][0], bf[nt][1]);
            }
        }

        #pragma unroll
        for (int i = 0; i < 2; i++) va[i] = nva[i];
        #pragma unroll
        for (int i = 0; i < 4; i++) kk[i] = nkk[i];
        #pragma unroll
        for (int q = 0; q < 4; q++) {
            ar[q][0] = nar[q][0];
            ar[q][1] = nar[q][1];
        }
        __syncthreads();   // MMA reads done before next writes
    }

    // ---- epilogue: J = SCALE * (C - vout (x) wk)
    #pragma unroll
    for (int q = 0; q < 4; q++) {
        const int bq = bq0 + q;
        const float* vo = g_vout + (size_t)bq * DH + v0;
        const float* wq = g_wk   + (size_t)bq * DH;
        float* o = out + (size_t)bq * DH * DH;
        const float vo0 = vo[m0 + g];
        const float vo1 = vo[m0 + g + 8];
        #pragma unroll
        for (int nt = 0; nt < 8; nt++) {
            const int col = wn * 64 + nt * 8 + 2 * t;
            const float w0 = wq[col];
            const float w1 = wq[col + 1];
            float2 r0, r1;
            r0.x = SCALE * (C[q][nt][0] - vo0 * w0);
            r0.y = SCALE * (C[q][nt][1] - vo0 * w1);
            r1.x = SCALE * (C[q][nt][2] - vo1 * w0);
            r1.y = SCALE * (C[q][nt][3] - vo1 * w1);
            *(float2*)&o[(size_t)(v0 + m0 + g) * DH + col]     = r0;
            *(float2*)&o[(size_t)(v0 + m0 + g + 8) * DH + col] = r1;
        }
    }
}

// ---------------------------------------------------------------------------
extern "C" void kernel_launch(void* const* d_in, const int* in_sizes, int n_in,
                              void* d_out, int out_size) {
    const float* Q = (const float*)d_in[0];
    const float* K = (const float*)d_in[1];
    const float* V = (const float*)d_in[2];
    float* out = (float*)d_out;

    scores_kernel<<<dim3(32, BATCH), 256>>>(Q, K);
    softmax_kernel<<<BATCH * NQ, 256>>>();
    aux_kernel<<<256, 256>>>(K, V);
    jac_kernel<<<BATCH * NQ / 2, 256>>>(K, V, out);
}